// round 15
// baseline (speedup 1.0000x reference)
#include <cuda_runtime.h>

#define BB 8
#define NN 4096
#define SS 1024
#define KK 32
#define M_TOTAL (BB*SS*KK)   // 262144
#define NBS (BB*SS)          // 8192

// ---------------- device scratch ----------------
__device__ float g_newxyz[NBS*3];            // (B,S,3)
__device__ int   g_ballidx[NBS*KK];          // (B,S,K)
__device__ float g_X0[67*M_TOTAL];
__device__ float g_Y0[64*M_TOTAL];
__device__ float g_Y1[64*M_TOTAL];
__device__ float g_mx2[128*NBS];
__device__ float g_mn2[128*NBS];
__device__ float2 g_WT0p[67*64];             // W transposed, duplicated pairs {w,w}
__device__ float2 g_WT1p[64*64];
__device__ float2 g_WT2p[64*128];
__device__ float g_sum0[64], g_sq0[64], g_sum1[64], g_sq1[64], g_sum2[128], g_sq2[128];

// ---------------- f32x2 packed helpers (bitwise identical per lane) ----------------
__device__ __forceinline__ unsigned long long ffma2(unsigned long long x, unsigned long long w,
                                                    unsigned long long a) {
    unsigned long long d;
    asm("fma.rn.f32x2 %0, %1, %2, %3;" : "=l"(d) : "l"(w), "l"(x), "l"(a));
    return d;
}
__device__ __forceinline__ unsigned long long add2(unsigned long long a, unsigned long long b) {
    unsigned long long d;
    asm("add.rn.f32x2 %0, %1, %2;" : "=l"(d) : "l"(a), "l"(b));
    return d;
}
__device__ __forceinline__ unsigned long long mul2(unsigned long long a, unsigned long long b) {
    unsigned long long d;
    asm("mul.rn.f32x2 %0, %1, %2;" : "=l"(d) : "l"(a), "l"(b));
    return d;
}
__device__ __forceinline__ unsigned long long pack2(float w) {
    unsigned long long d;
    asm("mov.b64 %0, {%1, %1};" : "=l"(d) : "f"(w));
    return d;
}
__device__ __forceinline__ unsigned long long packab(float a, float b) {
    unsigned long long d;
    asm("mov.b64 %0, {%1, %2};" : "=l"(d) : "f"(a), "f"(b));
    return d;
}
__device__ __forceinline__ float2 unpack2(unsigned long long v) {
    float2 r;
    asm("mov.b64 {%0, %1}, %2;" : "=f"(r.x), "=f"(r.y) : "l"(v));
    return r;
}
__device__ __forceinline__ float fneg(float x) {
    return __int_as_float(__float_as_int(x) ^ 0x80000000);
}
// BN affine from raw sums: identical formula/order everywhere -> bitwise identical
__device__ __forceinline__ void bn_affine(float sum, float sq, float g, float bt,
                                          float& a, float& c) {
    const float invM = 1.0f / (float)M_TOTAL;
    float mean = sum * invM;
    float var  = __fmaf_rn(-mean, mean, sq * invM);
    float inv  = 1.0f / sqrtf(var + 1e-5f);
    a = g * inv;
    c = __fmaf_rn(-mean, a, bt);
}

// ---------------- FPS ----------------
// one block per batch, 1024 threads, 4 points/thread packed as 2 f32x2 pairs.
__global__ void __launch_bounds__(1024) fps_kernel(const float* __restrict__ xyz,
                                                   float* __restrict__ out_newxyz_T)
{
    const int b = blockIdx.x;
    const int tid = threadIdx.x;
    const int lane = tid & 31, wid = tid >> 5;
    __shared__ unsigned sd[2][32];
    __shared__ unsigned si[2][32];
    extern __shared__ float sxyz[];   // 3*NN floats

    const float* xb = xyz + (size_t)b*3*NN;
    unsigned long long pxp[2], pyp[2], pzp[2];
    float dmin[4];
    {
        float px[4], py[4], pz[4];
#pragma unroll
        for (int j = 0; j < 4; ++j) {
            int i = tid + (j << 10);
            px[j] = xb[i]; py[j] = xb[NN + i]; pz[j] = xb[2*NN + i];
            sxyz[i] = px[j]; sxyz[NN + i] = py[j]; sxyz[2*NN + i] = pz[j];
            dmin[j] = 1e10f;
        }
        pxp[0] = packab(px[0], px[1]); pxp[1] = packab(px[2], px[3]);
        pyp[0] = packab(py[0], py[1]); pyp[1] = packab(py[2], py[3]);
        pzp[0] = packab(pz[0], pz[1]); pzp[1] = packab(pz[2], pz[3]);
    }
    __syncthreads();
    float cx = sxyz[0], cy = sxyz[NN], cz = sxyz[2*NN];
    if (tid == 0) {
        int o3 = (b*SS + 0)*3;
        g_newxyz[o3+0] = cx; g_newxyz[o3+1] = cy; g_newxyz[o3+2] = cz;
        out_newxyz_T[(b*3+0)*SS + 0] = cx;
        out_newxyz_T[(b*3+1)*SS + 0] = cy;
        out_newxyz_T[(b*3+2)*SS + 0] = cz;
    }

    for (int it = 1; it < SS; ++it) {
        const unsigned long long nx = pack2(fneg(cx));
        const unsigned long long ny = pack2(fneg(cy));
        const unsigned long long nz = pack2(fneg(cz));
        float d[4];
#pragma unroll
        for (int p = 0; p < 2; ++p) {
            unsigned long long dx = add2(pxp[p], nx);
            unsigned long long dy = add2(pyp[p], ny);
            unsigned long long dz = add2(pzp[p], nz);
            unsigned long long dd = add2(add2(mul2(dx,dx), mul2(dy,dy)), mul2(dz,dz));
            float2 f = unpack2(dd);
            d[2*p] = f.x; d[2*p+1] = f.y;
        }
#pragma unroll
        for (int j = 0; j < 4; ++j) dmin[j] = fminf(dmin[j], d[j]);
        float m = fmaxf(fmaxf(dmin[0], dmin[1]), fmaxf(dmin[2], dmin[3]));
        int j = (dmin[0] == m) ? 0 : ((dmin[1] == m) ? 1 : ((dmin[2] == m) ? 2 : 3));
        unsigned db   = __float_as_uint(m);
        unsigned idxv = (unsigned)(tid + (j << 10));
        unsigned wd = __reduce_max_sync(0xffffffffu, db);
        unsigned wi = __reduce_min_sync(0xffffffffu, (db == wd) ? idxv : 0xffffffffu);
        int buf = it & 1;
        if (lane == 0) { sd[buf][wid] = wd; si[buf][wid] = wi; }
        __syncthreads();
        unsigned d2 = sd[buf][lane], i2 = si[buf][lane];
        unsigned gd  = __reduce_max_sync(0xffffffffu, d2);
        unsigned far = __reduce_min_sync(0xffffffffu, (d2 == gd) ? i2 : 0xffffffffu);
        cx = sxyz[far]; cy = sxyz[NN + far]; cz = sxyz[2*NN + far];
        if (tid == (int)(far & 1023u)) {
            int o3 = (b*SS + it)*3;
            g_newxyz[o3+0] = cx; g_newxyz[o3+1] = cy; g_newxyz[o3+2] = cz;
            out_newxyz_T[(b*3+0)*SS + it] = cx;
            out_newxyz_T[(b*3+1)*SS + it] = cy;
            out_newxyz_T[(b*3+2)*SS + it] = cz;
        }
    }
}

// ---------------- ball query (+ tail block: W transpose into duplicated pairs) ----------------
__global__ void __launch_bounds__(256) ball_kernel(const float* __restrict__ xyz,
                                                   const float* __restrict__ W0,
                                                   const float* __restrict__ W1,
                                                   const float* __restrict__ W2)
{
    if (blockIdx.x == NBS/8) {
        const int t = threadIdx.x;
        for (int i = t; i < 67*64; i += 256) {
            int o = i & 63, c = i >> 6;
            float w = __ldg(W0 + o*67 + c);
            g_WT0p[i] = make_float2(w, w);
        }
        for (int i = t; i < 64*64; i += 256) {
            int o = i & 63, c = i >> 6;
            float w = __ldg(W1 + o*64 + c);
            g_WT1p[i] = make_float2(w, w);
        }
        for (int i = t; i < 64*128; i += 256) {
            int o = i & 127, c = i >> 7;
            float w = __ldg(W2 + o*64 + c);
            g_WT2p[i] = make_float2(w, w);
        }
        return;
    }
    const int w = (blockIdx.x * blockDim.x + threadIdx.x) >> 5;
    const int lane = threadIdx.x & 31;
    if (w >= NBS) return;
    const int b = w >> 10;

    const float cx = g_newxyz[w*3+0], cy = g_newxyz[w*3+1], cz = g_newxyz[w*3+2];
    const float s2 = __fadd_rn(__fadd_rn(__fmul_rn(cx,cx), __fmul_rn(cy,cy)), __fmul_rn(cz,cz));
    const float R2 = (float)(0.4*0.4);
    const float* xb = xyz + (size_t)b*3*NN;
    int total = 0, firstn = 0;
    int* outp = g_ballidx + w*KK;

    for (int base = 0; base < NN; base += 32) {
        int n = base + lane;
        float px = __ldg(xb + n), py = __ldg(xb + NN + n), pz = __ldg(xb + 2*NN + n);
        float n2  = __fadd_rn(__fadd_rn(__fmul_rn(px,px), __fmul_rn(py,py)), __fmul_rn(pz,pz));
        float dot = __fadd_rn(__fadd_rn(__fmul_rn(cx,px), __fmul_rn(cy,py)), __fmul_rn(cz,pz));
        float d   = __fadd_rn(__fadd_rn(__fmul_rn(-2.0f, dot), s2), n2);
        bool pred = !(d > R2);
        unsigned mask = __ballot_sync(0xffffffffu, pred);
        if (mask) {
            if (total == 0) firstn = base + __ffs(mask) - 1;
            if (pred) {
                int pos = total + __popc(mask & ((1u << lane) - 1u));
                if (pos < KK) outp[pos] = n;
            }
            total += __popc(mask);
            if (total >= KK) break;
        }
    }
    for (int p = total + lane; p < KK; p += 32) outp[p] = firstn;
}

// ---------------- gather / concat -> X0 (67, M); block 0 also zeroes BN stats ----------------
__global__ void __launch_bounds__(128) gather_kernel(const float* __restrict__ xyz,
                                                     const float* __restrict__ points)
{
    const int bs = blockIdx.x;            // 0..8191
    const int b = bs >> 10;
    const int tid = threadIdx.x;
    if (bs == 0) {
        if (tid < 64)  { g_sum0[tid]=0.f; g_sq0[tid]=0.f; g_sum1[tid]=0.f; g_sq1[tid]=0.f; }
        if (tid < 128) { g_sum2[tid]=0.f; g_sq2[tid]=0.f; }
    }
    __shared__ int sidx[KK];
    __shared__ float sc[3];
    if (tid < KK) sidx[tid] = g_ballidx[bs*KK + tid];
    if (tid < 3)  sc[tid]   = g_newxyz[bs*3 + tid];
    __syncthreads();

    const size_t m0 = (size_t)bs * KK;
    if (tid < 96) {
        int c = tid >> 5, k = tid & 31;
        float v = __fsub_rn(__ldg(&xyz[((size_t)b*3 + c)*NN + sidx[k]]), sc[c]);
        g_X0[(size_t)c*M_TOTAL + m0 + k] = v;
    }
    const int k = tid & 31, d0 = tid >> 5;   // d0 in 0..3
    const float* pb = points + (size_t)b*64*NN + sidx[k];
#pragma unroll
    for (int i = 0; i < 16; ++i) {
        int d = 4*i + d0;
        g_X0[(size_t)(3+d)*M_TOTAL + m0 + k] = __ldg(pb + (size_t)d*NN);
    }
}

// ---------------- GEMM layers 0/1 (chunked, double-buffered, remainder-aware) ----------------
// 256 threads (tx=lane, ty=warp 0..7). Tile: 256 cols x 64 channels; per-thread
// 8 cols x 8 channels. K in 16-row chunks, last chunk REM rows (exact).
// LAYER 1: computes BN affine from raw sums in-block (replaces stats kernel)
// and fuses BN+ReLU into X staging.
template<int CIN, int COUT, int LAYER>
__global__ void __launch_bounds__(256, 2) gemm_kernel(const float* __restrict__ bias,
                                                      const float* __restrict__ gamma,
                                                      const float* __restrict__ beta)
{
    constexpr int NCH = (CIN + 15) / 16;
    constexpr int REM = CIN - (NCH - 1) * 16;
    const float* Xg = (LAYER==0) ? g_X0 : g_Y0;
    float* Yg       = (LAYER==0) ? g_Y0 : g_Y1;
    const float2* WTp = (LAYER==0) ? g_WT0p : g_WT1p;
    float* sumArr   = (LAYER==0) ? g_sum0 : g_sum1;
    float* sqArr    = (LAYER==0) ? g_sq0  : g_sq1;

    extern __shared__ unsigned long long smem_u64[];
    unsigned long long* Wp = smem_u64;               // CIN*64 packed pairs
    float* Xs  = (float*)(smem_u64 + CIN*64);        // 2 * 16*256 floats
    float* as_ = Xs + 2*4096;                        // CIN
    float* cs_ = as_ + CIN;                          // CIN

    const int tid = threadIdx.x;
    const int m0  = blockIdx.x * 256;

    if (LAYER == 1) {
        if (tid < CIN) {
            float a, c;
            bn_affine(g_sum0[tid], g_sq0[tid], __ldg(gamma + tid), __ldg(beta + tid), a, c);
            as_[tid] = a; cs_[tid] = c;
        }
    }
    for (int i = tid; i < CIN*64; i += 256) {
        int c = i >> 6, o = i & 63;
        ((float2*)Wp)[i] = __ldg(WTp + c*COUT + o);
    }
    __syncthreads();

    // stage chunk 0
#pragma unroll
    for (int j = 0; j < 4; ++j) {
        int i = tid + (j << 8);
        int cl = i >> 6, q = i & 63;
        float4 v = __ldg((const float4*)(Xg + (size_t)cl*M_TOTAL + m0) + q);
        if (LAYER == 1) {
            float a = as_[cl], cc = cs_[cl];
            v.x = fmaxf(0.f, __fmaf_rn(v.x, a, cc));
            v.y = fmaxf(0.f, __fmaf_rn(v.y, a, cc));
            v.z = fmaxf(0.f, __fmaf_rn(v.z, a, cc));
            v.w = fmaxf(0.f, __fmaf_rn(v.w, a, cc));
        }
        *(float4*)(Xs + cl*256 + (q << 2)) = v;
    }
    __syncthreads();

    const int tx = tid & 31, ty = tid >> 5;
    unsigned long long acc[8][4];
#pragma unroll
    for (int r = 0; r < 8; ++r)
#pragma unroll
        for (int q = 0; q < 4; ++q) acc[r][q] = 0ull;

    int buf = 0;
#pragma unroll 1
    for (int ch = 0; ch < NCH - 1; ++ch) {
        const int nc0 = (ch + 1) << 4;
        float4 pre[4];
#pragma unroll
        for (int j = 0; j < 4; ++j) {
            int i = tid + (j << 8);
            int c = nc0 + (i >> 6);
            pre[j] = make_float4(0.f, 0.f, 0.f, 0.f);
            if (c < CIN)
                pre[j] = __ldg((const float4*)(Xg + (size_t)c*M_TOTAL + m0) + (i & 63));
        }
        const float* xb = Xs + buf*4096;
        const unsigned long long* wb = Wp + (ch << 4)*64 + (ty << 3);
#pragma unroll
        for (int kk = 0; kk < 16; ++kk) {
            ulonglong2 xA = *(const ulonglong2*)(xb + kk*256 + (tx << 2));
            ulonglong2 xB = *(const ulonglong2*)(xb + kk*256 + 128 + (tx << 2));
            const ulonglong2* wp = (const ulonglong2*)(wb + kk*64);
            ulonglong2 w01 = wp[0], w23 = wp[1], w45 = wp[2], w67 = wp[3];
            unsigned long long xv[4] = {xA.x, xA.y, xB.x, xB.y};
            unsigned long long wv[8] = {w01.x, w01.y, w23.x, w23.y,
                                        w45.x, w45.y, w67.x, w67.y};
#pragma unroll
            for (int r = 0; r < 8; ++r)
#pragma unroll
                for (int q = 0; q < 4; ++q)
                    acc[r][q] = ffma2(xv[q], wv[r], acc[r][q]);
        }
        {
            float* xd = Xs + (buf ^ 1)*4096;
#pragma unroll
            for (int j = 0; j < 4; ++j) {
                int i = tid + (j << 8);
                int cl = i >> 6, q = i & 63;
                float4 v = pre[j];
                if (LAYER == 1) {
                    int c = nc0 + cl;
                    if (c < CIN) {
                        float a = as_[c], cc = cs_[c];
                        v.x = fmaxf(0.f, __fmaf_rn(v.x, a, cc));
                        v.y = fmaxf(0.f, __fmaf_rn(v.y, a, cc));
                        v.z = fmaxf(0.f, __fmaf_rn(v.z, a, cc));
                        v.w = fmaxf(0.f, __fmaf_rn(v.w, a, cc));
                    }
                }
                *(float4*)(xd + cl*256 + (q << 2)) = v;
            }
        }
        __syncthreads();
        buf ^= 1;
    }
    // final chunk: REM rows only (skipped rows would be exact zeros)
    {
        const float* xb = Xs + buf*4096;
        const unsigned long long* wb = Wp + ((NCH-1) << 4)*64 + (ty << 3);
#pragma unroll
        for (int kk = 0; kk < REM; ++kk) {
            ulonglong2 xA = *(const ulonglong2*)(xb + kk*256 + (tx << 2));
            ulonglong2 xB = *(const ulonglong2*)(xb + kk*256 + 128 + (tx << 2));
            const ulonglong2* wp = (const ulonglong2*)(wb + kk*64);
            ulonglong2 w01 = wp[0], w23 = wp[1], w45 = wp[2], w67 = wp[3];
            unsigned long long xv[4] = {xA.x, xA.y, xB.x, xB.y};
            unsigned long long wv[8] = {w01.x, w01.y, w23.x, w23.y,
                                        w45.x, w45.y, w67.x, w67.y};
#pragma unroll
            for (int r = 0; r < 8; ++r)
#pragma unroll
                for (int q = 0; q < 4; ++q)
                    acc[r][q] = ffma2(xv[q], wv[r], acc[r][q]);
        }
    }

#pragma unroll
    for (int r = 0; r < 8; ++r) {
        int ch = (ty << 3) + r;
        float bv = __ldg(bias + ch);
        float o[8];
        {
            float2 p0 = unpack2(acc[r][0]), p1 = unpack2(acc[r][1]);
            float2 p2 = unpack2(acc[r][2]), p3 = unpack2(acc[r][3]);
            o[0]=p0.x+bv; o[1]=p0.y+bv; o[2]=p1.x+bv; o[3]=p1.y+bv;
            o[4]=p2.x+bv; o[5]=p2.y+bv; o[6]=p3.x+bv; o[7]=p3.y+bv;
        }
        float s = 0.f, s2 = 0.f;
#pragma unroll
        for (int j = 0; j < 8; ++j) {
            s += o[j];
            s2 = __fmaf_rn(o[j], o[j], s2);
        }
        float* yp = Yg + (size_t)ch*M_TOTAL + m0 + (tx << 2);
        *(float4*)yp         = make_float4(o[0],o[1],o[2],o[3]);
        *(float4*)(yp + 128) = make_float4(o[4],o[5],o[6],o[7]);
#pragma unroll
        for (int off = 16; off > 0; off >>= 1) {
            s  += __shfl_xor_sync(0xffffffffu, s,  off);
            s2 += __shfl_xor_sync(0xffffffffu, s2, off);
        }
        if (tx == 0) { atomicAdd(sumArr + ch, s); atomicAdd(sqArr + ch, s2); }
    }
}

// ---------------- GEMM layer 2: 512 threads, single pass over all 128 channels ----------------
// Tile: 256 cols x 128 channels; 16 warps, per-thread 8 cols x 8 channels
// (the proven per-thread shape). X staged+BN'd ONCE; W copied straight
// (g_WT2p is already in [c*128+o] layout). Fused max/min pool.
__global__ void __launch_bounds__(512, 1) gemm2_kernel(const float* __restrict__ bias,
                                                       const float* __restrict__ gamma,
                                                       const float* __restrict__ beta)
{
    constexpr int CIN = 64, COUT = 128, NCH = 4;

    extern __shared__ unsigned long long smem_u64[];
    unsigned long long* Wp = smem_u64;               // CIN*128 packed pairs
    float* Xs  = (float*)(smem_u64 + CIN*COUT);      // 2 * 16*256 floats
    float* as_ = Xs + 2*4096;                        // CIN
    float* cs_ = as_ + CIN;                          // CIN

    const int tid = threadIdx.x;
    const int m0  = blockIdx.x * 256;

    if (tid < CIN) {
        float a, c;
        bn_affine(g_sum1[tid], g_sq1[tid], __ldg(gamma + tid), __ldg(beta + tid), a, c);
        as_[tid] = a; cs_[tid] = c;
    }
    for (int i = tid; i < CIN*COUT; i += 512)
        ((float2*)Wp)[i] = __ldg(g_WT2p + i);
    __syncthreads();

    // stage chunk 0 (16 rows x 256 cols = 1024 float4; 2 per thread)
#pragma unroll
    for (int j = 0; j < 2; ++j) {
        int i = tid + (j << 9);
        int cl = i >> 6, q = i & 63;
        float4 v = __ldg((const float4*)(g_Y1 + (size_t)cl*M_TOTAL + m0) + q);
        float a = as_[cl], cc = cs_[cl];
        v.x = fmaxf(0.f, __fmaf_rn(v.x, a, cc));
        v.y = fmaxf(0.f, __fmaf_rn(v.y, a, cc));
        v.z = fmaxf(0.f, __fmaf_rn(v.z, a, cc));
        v.w = fmaxf(0.f, __fmaf_rn(v.w, a, cc));
        *(float4*)(Xs + cl*256 + (q << 2)) = v;
    }
    __syncthreads();

    const int tx = tid & 31, ty = tid >> 5;   // ty 0..15
    unsigned long long acc[8][4];
#pragma unroll
    for (int r = 0; r < 8; ++r)
#pragma unroll
        for (int q = 0; q < 4; ++q) acc[r][q] = 0ull;

    int buf = 0;
#pragma unroll 1
    for (int ch = 0; ch < NCH; ++ch) {
        const int nc0 = (ch + 1) << 4;
        const bool haveNext = (ch + 1 < NCH);
        float4 pre[2];
#pragma unroll
        for (int j = 0; j < 2; ++j) {
            int i = tid + (j << 9);
            int c = nc0 + (i >> 6);
            pre[j] = make_float4(0.f, 0.f, 0.f, 0.f);
            if (haveNext)
                pre[j] = __ldg((const float4*)(g_Y1 + (size_t)c*M_TOTAL + m0) + (i & 63));
        }
        const float* xb = Xs + buf*4096;
        const unsigned long long* wb = Wp + (ch << 4)*COUT + (ty << 3);
#pragma unroll
        for (int kk = 0; kk < 16; ++kk) {
            ulonglong2 xA = *(const ulonglong2*)(xb + kk*256 + (tx << 2));
            ulonglong2 xB = *(const ulonglong2*)(xb + kk*256 + 128 + (tx << 2));
            const ulonglong2* wp = (const ulonglong2*)(wb + kk*COUT);
            ulonglong2 w01 = wp[0], w23 = wp[1], w45 = wp[2], w67 = wp[3];
            unsigned long long xv[4] = {xA.x, xA.y, xB.x, xB.y};
            unsigned long long wv[8] = {w01.x, w01.y, w23.x, w23.y,
                                        w45.x, w45.y, w67.x, w67.y};
#pragma unroll
            for (int r = 0; r < 8; ++r)
#pragma unroll
                for (int q = 0; q < 4; ++q)
                    acc[r][q] = ffma2(xv[q], wv[r], acc[r][q]);
        }
        if (haveNext) {
            float* xd = Xs + (buf ^ 1)*4096;
#pragma unroll
            for (int j = 0; j < 2; ++j) {
                int i = tid + (j << 9);
                int cl = i >> 6, q = i & 63;
                float4 v = pre[j];
                int c = nc0 + cl;
                float a = as_[c], cc = cs_[c];
                v.x = fmaxf(0.f, __fmaf_rn(v.x, a, cc));
                v.y = fmaxf(0.f, __fmaf_rn(v.y, a, cc));
                v.z = fmaxf(0.f, __fmaf_rn(v.z, a, cc));
                v.w = fmaxf(0.f, __fmaf_rn(v.w, a, cc));
                *(float4*)(xd + cl*256 + (q << 2)) = v;
            }
        }
        __syncthreads();
        buf ^= 1;
    }

    const int m0q = m0 >> 5;   // first k-group of this tile (8 groups)
#pragma unroll
    for (int r = 0; r < 8; ++r) {
        int ch = (ty << 3) + r;
        float bv = __ldg(bias + ch);
        float o[8];
        {
            float2 p0 = unpack2(acc[r][0]), p1 = unpack2(acc[r][1]);
            float2 p2 = unpack2(acc[r][2]), p3 = unpack2(acc[r][3]);
            o[0]=p0.x+bv; o[1]=p0.y+bv; o[2]=p1.x+bv; o[3]=p1.y+bv;
            o[4]=p2.x+bv; o[5]=p2.y+bv; o[6]=p3.x+bv; o[7]=p3.y+bv;
        }
        float s = 0.f, s2 = 0.f;
#pragma unroll
        for (int j = 0; j < 8; ++j) {
            s += o[j];
            s2 = __fmaf_rn(o[j], o[j], s2);
        }
        // pool over K: quad A in group tx>>3, quad B in group 4+(tx>>3)
        float mxA = fmaxf(fmaxf(o[0],o[1]), fmaxf(o[2],o[3]));
        float mnA = fminf(fminf(o[0],o[1]), fminf(o[2],o[3]));
        float mxB = fmaxf(fmaxf(o[4],o[5]), fmaxf(o[6],o[7]));
        float mnB = fminf(fminf(o[4],o[5]), fminf(o[6],o[7]));
#pragma unroll
        for (int off = 1; off < 8; off <<= 1) {
            mxA = fmaxf(mxA, __shfl_xor_sync(0xffffffffu, mxA, off));
            mnA = fminf(mnA, __shfl_xor_sync(0xffffffffu, mnA, off));
            mxB = fmaxf(mxB, __shfl_xor_sync(0xffffffffu, mxB, off));
            mnB = fminf(mnB, __shfl_xor_sync(0xffffffffu, mnB, off));
        }
        if ((tx & 7) == 0) {
            int bsA = m0q + (tx >> 3);
            int bsB = m0q + 4 + (tx >> 3);
            g_mx2[ch*NBS + bsA] = mxA;
            g_mn2[ch*NBS + bsA] = mnA;
            g_mx2[ch*NBS + bsB] = mxB;
            g_mn2[ch*NBS + bsB] = mnB;
        }
#pragma unroll
        for (int off = 16; off > 0; off >>= 1) {
            s  += __shfl_xor_sync(0xffffffffu, s,  off);
            s2 += __shfl_xor_sync(0xffffffffu, s2, off);
        }
        if (tx == 0) { atomicAdd(g_sum2 + ch, s); atomicAdd(g_sq2 + ch, s2); }
    }
}

// ---------------- finalize: BN affine from sums + ReLU on pooled extrema ----------------
// max_k relu(a*y+c) == relu(a*(a>=0 ? max_k y : min_k y) + c)  (fmaf monotone in y)
__global__ void __launch_bounds__(256) finalize_kernel(float* __restrict__ out,
                                                       const float* __restrict__ gamma,
                                                       const float* __restrict__ beta)
{
    int gid = blockIdx.x * blockDim.x + threadIdx.x;
    if (gid >= BB*128*SS) return;
    int s = gid & (SS-1);
    int o = (gid >> 10) & 127;
    int b = gid >> 17;
    float a, c;
    bn_affine(g_sum2[o], g_sq2[o], __ldg(gamma + o), __ldg(beta + o), a, c);
    int bs = (b << 10) + s;
    float v = (a >= 0.f) ? g_mx2[o*NBS + bs] : g_mn2[o*NBS + bs];
    out[gid] = fmaxf(0.f, __fmaf_rn(v, a, c));
}

// ---------------- launch ----------------
extern "C" void kernel_launch(void* const* d_in, const int* in_sizes, int n_in,
                              void* d_out, int out_size)
{
    const float* xyz    = (const float*)d_in[0];
    const float* points = (const float*)d_in[1];
    const float* W0  = (const float*)d_in[2];
    const float* b0  = (const float*)d_in[3];
    const float* g0  = (const float*)d_in[4];
    const float* bt0 = (const float*)d_in[5];
    const float* W1  = (const float*)d_in[6];
    const float* b1  = (const float*)d_in[7];
    const float* g1  = (const float*)d_in[8];
    const float* bt1 = (const float*)d_in[9];
    const float* W2  = (const float*)d_in[10];
    const float* b2  = (const float*)d_in[11];
    const float* g2  = (const float*)d_in[12];
    const float* bt2 = (const float*)d_in[13];

    float* out = (float*)d_out;
    float* out_feat = out + BB*3*SS;

    const int smf = 3*NN*4;                              // 49152 (fps xyz stage)
    const int sm0 = 67*64*8 + 2*4096*4 + 2*67*4;         // 67608
    const int sm1 = 64*64*8 + 2*4096*4 + 2*64*4;         // 66048
    const int sm2 = 64*128*8 + 2*4096*4 + 2*64*4;        // 98816
    cudaFuncSetAttribute(fps_kernel, cudaFuncAttributeMaxDynamicSharedMemorySize, smf);
    cudaFuncSetAttribute(gemm_kernel<67,64,0>, cudaFuncAttributeMaxDynamicSharedMemorySize, sm0);
    cudaFuncSetAttribute(gemm_kernel<64,64,1>, cudaFuncAttributeMaxDynamicSharedMemorySize, sm1);
    cudaFuncSetAttribute(gemm2_kernel,         cudaFuncAttributeMaxDynamicSharedMemorySize, sm2);

    fps_kernel<<<BB, 1024, smf>>>(xyz, out);
    ball_kernel<<<NBS/8 + 1, 256>>>(xyz, W0, W1, W2);    // +1 block preps W pairs
    gather_kernel<<<NBS, 128>>>(xyz, points);            // block 0 zeroes stats

    gemm_kernel<67,64,0><<<M_TOTAL/256, 256, sm0>>>(b0, nullptr, nullptr);
    gemm_kernel<64,64,1><<<M_TOTAL/256, 256, sm1>>>(b1, g0, bt0);
    gemm2_kernel<<<M_TOTAL/256, 512, sm2>>>(b2, g1, bt1);

    finalize_kernel<<<(BB*128*SS)/256, 256>>>(out_feat, g2, bt2);
}

// round 16
// speedup vs baseline: 1.0376x; 1.0376x over previous
#include <cuda_runtime.h>

#define BB 8
#define NN 4096
#define SS 1024
#define KK 32
#define M_TOTAL (BB*SS*KK)   // 262144
#define NBS (BB*SS)          // 8192

// ---------------- device scratch ----------------
__device__ float g_newxyz[NBS*3];            // (B,S,3)
__device__ int   g_ballidx[NBS*KK];          // (B,S,K)
__device__ float g_X0[67*M_TOTAL];
__device__ float g_Y0[64*M_TOTAL];
__device__ float g_Y1[64*M_TOTAL];
__device__ float g_mx2[128*NBS];
__device__ float g_mn2[128*NBS];
__device__ float2 g_WT0p[67*64];             // W transposed, duplicated pairs {w,w}
__device__ float2 g_WT1p[64*64];
__device__ float2 g_WT2p[64*128];
__device__ float g_sum0[64], g_sq0[64], g_sum1[64], g_sq1[64], g_sum2[128], g_sq2[128];

// ---------------- f32x2 packed helpers (bitwise identical per lane) ----------------
__device__ __forceinline__ unsigned long long ffma2(unsigned long long x, unsigned long long w,
                                                    unsigned long long a) {
    unsigned long long d;
    asm("fma.rn.f32x2 %0, %1, %2, %3;" : "=l"(d) : "l"(w), "l"(x), "l"(a));
    return d;
}
__device__ __forceinline__ unsigned long long add2(unsigned long long a, unsigned long long b) {
    unsigned long long d;
    asm("add.rn.f32x2 %0, %1, %2;" : "=l"(d) : "l"(a), "l"(b));
    return d;
}
__device__ __forceinline__ unsigned long long mul2(unsigned long long a, unsigned long long b) {
    unsigned long long d;
    asm("mul.rn.f32x2 %0, %1, %2;" : "=l"(d) : "l"(a), "l"(b));
    return d;
}
__device__ __forceinline__ unsigned long long pack2(float w) {
    unsigned long long d;
    asm("mov.b64 %0, {%1, %1};" : "=l"(d) : "f"(w));
    return d;
}
__device__ __forceinline__ unsigned long long packab(float a, float b) {
    unsigned long long d;
    asm("mov.b64 %0, {%1, %2};" : "=l"(d) : "f"(a), "f"(b));
    return d;
}
__device__ __forceinline__ float2 unpack2(unsigned long long v) {
    float2 r;
    asm("mov.b64 {%0, %1}, %2;" : "=f"(r.x), "=f"(r.y) : "l"(v));
    return r;
}
__device__ __forceinline__ float fneg(float x) {
    return __int_as_float(__float_as_int(x) ^ 0x80000000);
}
// BN affine from raw sums: identical formula/order everywhere -> bitwise identical
__device__ __forceinline__ void bn_affine(float sum, float sq, float g, float bt,
                                          float& a, float& c) {
    const float invM = 1.0f / (float)M_TOTAL;
    float mean = sum * invM;
    float var  = __fmaf_rn(-mean, mean, sq * invM);
    float inv  = 1.0f / sqrtf(var + 1e-5f);
    a = g * inv;
    c = __fmaf_rn(-mean, a, bt);
}

// ---------------- FPS ----------------
// one block per batch, 1024 threads, 4 points/thread packed as 2 f32x2 pairs.
__global__ void __launch_bounds__(1024) fps_kernel(const float* __restrict__ xyz,
                                                   float* __restrict__ out_newxyz_T)
{
    const int b = blockIdx.x;
    const int tid = threadIdx.x;
    const int lane = tid & 31, wid = tid >> 5;
    __shared__ unsigned sd[2][32];
    __shared__ unsigned si[2][32];
    extern __shared__ float sxyz[];   // 3*NN floats

    const float* xb = xyz + (size_t)b*3*NN;
    unsigned long long pxp[2], pyp[2], pzp[2];
    float dmin[4];
    {
        float px[4], py[4], pz[4];
#pragma unroll
        for (int j = 0; j < 4; ++j) {
            int i = tid + (j << 10);
            px[j] = xb[i]; py[j] = xb[NN + i]; pz[j] = xb[2*NN + i];
            sxyz[i] = px[j]; sxyz[NN + i] = py[j]; sxyz[2*NN + i] = pz[j];
            dmin[j] = 1e10f;
        }
        pxp[0] = packab(px[0], px[1]); pxp[1] = packab(px[2], px[3]);
        pyp[0] = packab(py[0], py[1]); pyp[1] = packab(py[2], py[3]);
        pzp[0] = packab(pz[0], pz[1]); pzp[1] = packab(pz[2], pz[3]);
    }
    __syncthreads();
    float cx = sxyz[0], cy = sxyz[NN], cz = sxyz[2*NN];
    if (tid == 0) {
        int o3 = (b*SS + 0)*3;
        g_newxyz[o3+0] = cx; g_newxyz[o3+1] = cy; g_newxyz[o3+2] = cz;
        out_newxyz_T[(b*3+0)*SS + 0] = cx;
        out_newxyz_T[(b*3+1)*SS + 0] = cy;
        out_newxyz_T[(b*3+2)*SS + 0] = cz;
    }

    for (int it = 1; it < SS; ++it) {
        const unsigned long long nx = pack2(fneg(cx));
        const unsigned long long ny = pack2(fneg(cy));
        const unsigned long long nz = pack2(fneg(cz));
        float d[4];
#pragma unroll
        for (int p = 0; p < 2; ++p) {
            unsigned long long dx = add2(pxp[p], nx);
            unsigned long long dy = add2(pyp[p], ny);
            unsigned long long dz = add2(pzp[p], nz);
            unsigned long long dd = add2(add2(mul2(dx,dx), mul2(dy,dy)), mul2(dz,dz));
            float2 f = unpack2(dd);
            d[2*p] = f.x; d[2*p+1] = f.y;
        }
#pragma unroll
        for (int j = 0; j < 4; ++j) dmin[j] = fminf(dmin[j], d[j]);
        float m = fmaxf(fmaxf(dmin[0], dmin[1]), fmaxf(dmin[2], dmin[3]));
        int j = (dmin[0] == m) ? 0 : ((dmin[1] == m) ? 1 : ((dmin[2] == m) ? 2 : 3));
        unsigned db   = __float_as_uint(m);
        unsigned idxv = (unsigned)(tid + (j << 10));
        unsigned wd = __reduce_max_sync(0xffffffffu, db);
        unsigned wi = __reduce_min_sync(0xffffffffu, (db == wd) ? idxv : 0xffffffffu);
        int buf = it & 1;
        if (lane == 0) { sd[buf][wid] = wd; si[buf][wid] = wi; }
        __syncthreads();
        unsigned d2 = sd[buf][lane], i2 = si[buf][lane];
        unsigned gd  = __reduce_max_sync(0xffffffffu, d2);
        unsigned far = __reduce_min_sync(0xffffffffu, (d2 == gd) ? i2 : 0xffffffffu);
        cx = sxyz[far]; cy = sxyz[NN + far]; cz = sxyz[2*NN + far];
        if (tid == (int)(far & 1023u)) {
            int o3 = (b*SS + it)*3;
            g_newxyz[o3+0] = cx; g_newxyz[o3+1] = cy; g_newxyz[o3+2] = cz;
            out_newxyz_T[(b*3+0)*SS + it] = cx;
            out_newxyz_T[(b*3+1)*SS + it] = cy;
            out_newxyz_T[(b*3+2)*SS + it] = cz;
        }
    }
}

// ---------------- ball query (+ tail block: W transpose into duplicated pairs) ----------------
__global__ void __launch_bounds__(256) ball_kernel(const float* __restrict__ xyz,
                                                   const float* __restrict__ W0,
                                                   const float* __restrict__ W1,
                                                   const float* __restrict__ W2)
{
    if (blockIdx.x == NBS/8) {
        const int t = threadIdx.x;
        for (int i = t; i < 67*64; i += 256) {
            int o = i & 63, c = i >> 6;
            float w = __ldg(W0 + o*67 + c);
            g_WT0p[i] = make_float2(w, w);
        }
        for (int i = t; i < 64*64; i += 256) {
            int o = i & 63, c = i >> 6;
            float w = __ldg(W1 + o*64 + c);
            g_WT1p[i] = make_float2(w, w);
        }
        for (int i = t; i < 64*128; i += 256) {
            int o = i & 127, c = i >> 7;
            float w = __ldg(W2 + o*64 + c);
            g_WT2p[i] = make_float2(w, w);
        }
        return;
    }
    const int w = (blockIdx.x * blockDim.x + threadIdx.x) >> 5;
    const int lane = threadIdx.x & 31;
    if (w >= NBS) return;
    const int b = w >> 10;

    const float cx = g_newxyz[w*3+0], cy = g_newxyz[w*3+1], cz = g_newxyz[w*3+2];
    const float s2 = __fadd_rn(__fadd_rn(__fmul_rn(cx,cx), __fmul_rn(cy,cy)), __fmul_rn(cz,cz));
    const float R2 = (float)(0.4*0.4);
    const float* xb = xyz + (size_t)b*3*NN;
    int total = 0, firstn = 0;
    int* outp = g_ballidx + w*KK;

    for (int base = 0; base < NN; base += 32) {
        int n = base + lane;
        float px = __ldg(xb + n), py = __ldg(xb + NN + n), pz = __ldg(xb + 2*NN + n);
        float n2  = __fadd_rn(__fadd_rn(__fmul_rn(px,px), __fmul_rn(py,py)), __fmul_rn(pz,pz));
        float dot = __fadd_rn(__fadd_rn(__fmul_rn(cx,px), __fmul_rn(cy,py)), __fmul_rn(cz,pz));
        float d   = __fadd_rn(__fadd_rn(__fmul_rn(-2.0f, dot), s2), n2);
        bool pred = !(d > R2);
        unsigned mask = __ballot_sync(0xffffffffu, pred);
        if (mask) {
            if (total == 0) firstn = base + __ffs(mask) - 1;
            if (pred) {
                int pos = total + __popc(mask & ((1u << lane) - 1u));
                if (pos < KK) outp[pos] = n;
            }
            total += __popc(mask);
            if (total >= KK) break;
        }
    }
    for (int p = total + lane; p < KK; p += 32) outp[p] = firstn;
}

// ---------------- gather / concat -> X0 (67, M); block 0 also zeroes BN stats ----------------
__global__ void __launch_bounds__(128) gather_kernel(const float* __restrict__ xyz,
                                                     const float* __restrict__ points)
{
    const int bs = blockIdx.x;            // 0..8191
    const int b = bs >> 10;
    const int tid = threadIdx.x;
    if (bs == 0) {
        if (tid < 64)  { g_sum0[tid]=0.f; g_sq0[tid]=0.f; g_sum1[tid]=0.f; g_sq1[tid]=0.f; }
        if (tid < 128) { g_sum2[tid]=0.f; g_sq2[tid]=0.f; }
    }
    __shared__ int sidx[KK];
    __shared__ float sc[3];
    if (tid < KK) sidx[tid] = g_ballidx[bs*KK + tid];
    if (tid < 3)  sc[tid]   = g_newxyz[bs*3 + tid];
    __syncthreads();

    const size_t m0 = (size_t)bs * KK;
    if (tid < 96) {
        int c = tid >> 5, k = tid & 31;
        float v = __fsub_rn(__ldg(&xyz[((size_t)b*3 + c)*NN + sidx[k]]), sc[c]);
        g_X0[(size_t)c*M_TOTAL + m0 + k] = v;
    }
    const int k = tid & 31, d0 = tid >> 5;   // d0 in 0..3
    const float* pb = points + (size_t)b*64*NN + sidx[k];
#pragma unroll
    for (int i = 0; i < 16; ++i) {
        int d = 4*i + d0;
        g_X0[(size_t)(3+d)*M_TOTAL + m0 + k] = __ldg(pb + (size_t)d*NN);
    }
}

// ---------------- GEMM (chunked, double-buffered, remainder-aware) ----------------
// 256 threads (tx=lane, ty=warp 0..7). Tile: 256 cols x 64 channels; per-thread
// 8 cols x 8 channels. K in 16-row chunks, last chunk REM rows (exact).
// gridDim.y selects the 64-channel half for LAYER 2.
// LAYER 1,2: BN affine computed in-block from raw sums (no stats kernel),
// fused BN+ReLU on X staging. LAYER 2: fused max/min pool.
template<int CIN, int COUT, int LAYER>
__global__ void __launch_bounds__(256, 2) gemm_kernel(const float* __restrict__ bias,
                                                      const float* __restrict__ gamma,
                                                      const float* __restrict__ beta)
{
    constexpr int NCH = (CIN + 15) / 16;
    constexpr int REM = CIN - (NCH - 1) * 16;
    const float* Xg = (LAYER==0) ? g_X0 : ((LAYER==1) ? g_Y0 : g_Y1);
    float* Yg       = (LAYER==0) ? g_Y0 : g_Y1;           // unused for LAYER==2
    const float2* WTp = (LAYER==0) ? g_WT0p : ((LAYER==1) ? g_WT1p : g_WT2p);
    float* sumArr   = (LAYER==0) ? g_sum0 : ((LAYER==1) ? g_sum1 : g_sum2);
    float* sqArr    = (LAYER==0) ? g_sq0  : ((LAYER==1) ? g_sq1  : g_sq2);
    const float* sumPrev = (LAYER==1) ? g_sum0 : g_sum1;
    const float* sqPrev  = (LAYER==1) ? g_sq0  : g_sq1;

    extern __shared__ unsigned long long smem_u64[];
    unsigned long long* Wp = smem_u64;               // CIN*64 packed pairs
    float* Xs  = (float*)(smem_u64 + CIN*64);        // 2 * 16*256 floats
    float* as_ = Xs + 2*4096;                        // CIN
    float* cs_ = as_ + CIN;                          // CIN

    const int tid = threadIdx.x;
    const int m0  = blockIdx.x * 256;
    const int ob  = blockIdx.y * 64;

    if (LAYER >= 1) {
        if (tid < CIN) {
            float a, c;
            bn_affine(sumPrev[tid], sqPrev[tid], __ldg(gamma + tid), __ldg(beta + tid), a, c);
            as_[tid] = a; cs_[tid] = c;
        }
    }
    for (int i = tid; i < CIN*64; i += 256) {
        int c = i >> 6, o = i & 63;
        ((float2*)Wp)[i] = __ldg(WTp + c*COUT + ob + o);
    }
    __syncthreads();

    // stage chunk 0
#pragma unroll
    for (int j = 0; j < 4; ++j) {
        int i = tid + (j << 8);
        int cl = i >> 6, q = i & 63;
        float4 v = __ldg((const float4*)(Xg + (size_t)cl*M_TOTAL + m0) + q);
        if (LAYER >= 1) {
            float a = as_[cl], cc = cs_[cl];
            v.x = fmaxf(0.f, __fmaf_rn(v.x, a, cc));
            v.y = fmaxf(0.f, __fmaf_rn(v.y, a, cc));
            v.z = fmaxf(0.f, __fmaf_rn(v.z, a, cc));
            v.w = fmaxf(0.f, __fmaf_rn(v.w, a, cc));
        }
        *(float4*)(Xs + cl*256 + (q << 2)) = v;
    }
    __syncthreads();

    const int tx = tid & 31, ty = tid >> 5;
    unsigned long long acc[8][4];
#pragma unroll
    for (int r = 0; r < 8; ++r)
#pragma unroll
        for (int q = 0; q < 4; ++q) acc[r][q] = 0ull;

    int buf = 0;
#pragma unroll 1
    for (int ch = 0; ch < NCH - 1; ++ch) {
        const int nc0 = (ch + 1) << 4;
        float4 pre[4];
#pragma unroll
        for (int j = 0; j < 4; ++j) {
            int i = tid + (j << 8);
            int c = nc0 + (i >> 6);
            pre[j] = make_float4(0.f, 0.f, 0.f, 0.f);
            if (c < CIN)
                pre[j] = __ldg((const float4*)(Xg + (size_t)c*M_TOTAL + m0) + (i & 63));
        }
        const float* xb = Xs + buf*4096;
        const unsigned long long* wb = Wp + (ch << 4)*64 + (ty << 3);
#pragma unroll
        for (int kk = 0; kk < 16; ++kk) {
            ulonglong2 xA = *(const ulonglong2*)(xb + kk*256 + (tx << 2));
            ulonglong2 xB = *(const ulonglong2*)(xb + kk*256 + 128 + (tx << 2));
            const ulonglong2* wp = (const ulonglong2*)(wb + kk*64);
            ulonglong2 w01 = wp[0], w23 = wp[1], w45 = wp[2], w67 = wp[3];
            unsigned long long xv[4] = {xA.x, xA.y, xB.x, xB.y};
            unsigned long long wv[8] = {w01.x, w01.y, w23.x, w23.y,
                                        w45.x, w45.y, w67.x, w67.y};
#pragma unroll
            for (int r = 0; r < 8; ++r)
#pragma unroll
                for (int q = 0; q < 4; ++q)
                    acc[r][q] = ffma2(xv[q], wv[r], acc[r][q]);
        }
        {
            float* xd = Xs + (buf ^ 1)*4096;
#pragma unroll
            for (int j = 0; j < 4; ++j) {
                int i = tid + (j << 8);
                int cl = i >> 6, q = i & 63;
                float4 v = pre[j];
                if (LAYER >= 1) {
                    int c = nc0 + cl;
                    if (c < CIN) {
                        float a = as_[c], cc = cs_[c];
                        v.x = fmaxf(0.f, __fmaf_rn(v.x, a, cc));
                        v.y = fmaxf(0.f, __fmaf_rn(v.y, a, cc));
                        v.z = fmaxf(0.f, __fmaf_rn(v.z, a, cc));
                        v.w = fmaxf(0.f, __fmaf_rn(v.w, a, cc));
                    }
                }
                *(float4*)(xd + cl*256 + (q << 2)) = v;
            }
        }
        __syncthreads();
        buf ^= 1;
    }
    // final chunk: REM rows only (skipped rows would be exact zeros)
    {
        const float* xb = Xs + buf*4096;
        const unsigned long long* wb = Wp + ((NCH-1) << 4)*64 + (ty << 3);
#pragma unroll
        for (int kk = 0; kk < REM; ++kk) {
            ulonglong2 xA = *(const ulonglong2*)(xb + kk*256 + (tx << 2));
            ulonglong2 xB = *(const ulonglong2*)(xb + kk*256 + 128 + (tx << 2));
            const ulonglong2* wp = (const ulonglong2*)(wb + kk*64);
            ulonglong2 w01 = wp[0], w23 = wp[1], w45 = wp[2], w67 = wp[3];
            unsigned long long xv[4] = {xA.x, xA.y, xB.x, xB.y};
            unsigned long long wv[8] = {w01.x, w01.y, w23.x, w23.y,
                                        w45.x, w45.y, w67.x, w67.y};
#pragma unroll
            for (int r = 0; r < 8; ++r)
#pragma unroll
                for (int q = 0; q < 4; ++q)
                    acc[r][q] = ffma2(xv[q], wv[r], acc[r][q]);
        }
    }

    const int m0q = m0 >> 5;   // first k-group of this tile (8 groups)
#pragma unroll
    for (int r = 0; r < 8; ++r) {
        int ch = ob + (ty << 3) + r;
        float bv = __ldg(bias + ch);
        float o[8];
        {
            float2 p0 = unpack2(acc[r][0]), p1 = unpack2(acc[r][1]);
            float2 p2 = unpack2(acc[r][2]), p3 = unpack2(acc[r][3]);
            o[0]=p0.x+bv; o[1]=p0.y+bv; o[2]=p1.x+bv; o[3]=p1.y+bv;
            o[4]=p2.x+bv; o[5]=p2.y+bv; o[6]=p3.x+bv; o[7]=p3.y+bv;
        }
        float s = 0.f, s2 = 0.f;
#pragma unroll
        for (int j = 0; j < 8; ++j) {
            s += o[j];
            s2 = __fmaf_rn(o[j], o[j], s2);
        }
        if (LAYER < 2) {
            float* yp = Yg + (size_t)ch*M_TOTAL + m0 + (tx << 2);
            *(float4*)yp         = make_float4(o[0],o[1],o[2],o[3]);
            *(float4*)(yp + 128) = make_float4(o[4],o[5],o[6],o[7]);
        } else {
            // pool over K: quad A in group tx>>3, quad B in group 4+(tx>>3)
            float mxA = fmaxf(fmaxf(o[0],o[1]), fmaxf(o[2],o[3]));
            float mnA = fminf(fminf(o[0],o[1]), fminf(o[2],o[3]));
            float mxB = fmaxf(fmaxf(o[4],o[5]), fmaxf(o[6],o[7]));
            float mnB = fminf(fminf(o[4],o[5]), fminf(o[6],o[7]));
#pragma unroll
            for (int off = 1; off < 8; off <<= 1) {
                mxA = fmaxf(mxA, __shfl_xor_sync(0xffffffffu, mxA, off));
                mnA = fminf(mnA, __shfl_xor_sync(0xffffffffu, mnA, off));
                mxB = fmaxf(mxB, __shfl_xor_sync(0xffffffffu, mxB, off));
                mnB = fminf(mnB, __shfl_xor_sync(0xffffffffu, mnB, off));
            }
            if ((tx & 7) == 0) {
                int bsA = m0q + (tx >> 3);
                int bsB = m0q + 4 + (tx >> 3);
                g_mx2[ch*NBS + bsA] = mxA;
                g_mn2[ch*NBS + bsA] = mnA;
                g_mx2[ch*NBS + bsB] = mxB;
                g_mn2[ch*NBS + bsB] = mnB;
            }
        }
#pragma unroll
        for (int off = 16; off > 0; off >>= 1) {
            s  += __shfl_xor_sync(0xffffffffu, s,  off);
            s2 += __shfl_xor_sync(0xffffffffu, s2, off);
        }
        if (tx == 0) { atomicAdd(sumArr + ch, s); atomicAdd(sqArr + ch, s2); }
    }
}

// ---------------- finalize: BN affine from sums + ReLU on pooled extrema ----------------
// max_k relu(a*y+c) == relu(a*(a>=0 ? max_k y : min_k y) + c)  (fmaf monotone in y)
__global__ void __launch_bounds__(256) finalize_kernel(float* __restrict__ out,
                                                       const float* __restrict__ gamma,
                                                       const float* __restrict__ beta)
{
    int gid = blockIdx.x * blockDim.x + threadIdx.x;
    if (gid >= BB*128*SS) return;
    int s = gid & (SS-1);
    int o = (gid >> 10) & 127;
    int b = gid >> 17;
    float a, c;
    bn_affine(g_sum2[o], g_sq2[o], __ldg(gamma + o), __ldg(beta + o), a, c);
    int bs = (b << 10) + s;
    float v = (a >= 0.f) ? g_mx2[o*NBS + bs] : g_mn2[o*NBS + bs];
    out[gid] = fmaxf(0.f, __fmaf_rn(v, a, c));
}

// ---------------- launch ----------------
extern "C" void kernel_launch(void* const* d_in, const int* in_sizes, int n_in,
                              void* d_out, int out_size)
{
    const float* xyz    = (const float*)d_in[0];
    const float* points = (const float*)d_in[1];
    const float* W0  = (const float*)d_in[2];
    const float* b0  = (const float*)d_in[3];
    const float* g0  = (const float*)d_in[4];
    const float* bt0 = (const float*)d_in[5];
    const float* W1  = (const float*)d_in[6];
    const float* b1  = (const float*)d_in[7];
    const float* g1  = (const float*)d_in[8];
    const float* bt1 = (const float*)d_in[9];
    const float* W2  = (const float*)d_in[10];
    const float* b2  = (const float*)d_in[11];
    const float* g2  = (const float*)d_in[12];
    const float* bt2 = (const float*)d_in[13];

    float* out = (float*)d_out;
    float* out_feat = out + BB*3*SS;

    const int smf = 3*NN*4;                              // 49152 (fps xyz stage)
    const int sm0 = 67*64*8 + 2*4096*4 + 2*67*4;         // 67608
    const int sm1 = 64*64*8 + 2*4096*4 + 2*64*4;         // 66048
    const int sm2 = sm1;
    cudaFuncSetAttribute(fps_kernel, cudaFuncAttributeMaxDynamicSharedMemorySize, smf);
    cudaFuncSetAttribute(gemm_kernel<67,64,0>,  cudaFuncAttributeMaxDynamicSharedMemorySize, sm0);
    cudaFuncSetAttribute(gemm_kernel<64,64,1>,  cudaFuncAttributeMaxDynamicSharedMemorySize, sm1);
    cudaFuncSetAttribute(gemm_kernel<64,128,2>, cudaFuncAttributeMaxDynamicSharedMemorySize, sm2);

    fps_kernel<<<BB, 1024, smf>>>(xyz, out);
    ball_kernel<<<NBS/8 + 1, 256>>>(xyz, W0, W1, W2);    // +1 block preps W pairs
    gather_kernel<<<NBS, 128>>>(xyz, points);            // block 0 zeroes stats

    gemm_kernel<67,64,0><<<dim3(M_TOTAL/256, 1), 256, sm0>>>(b0, nullptr, nullptr);
    gemm_kernel<64,64,1><<<dim3(M_TOTAL/256, 1), 256, sm1>>>(b1, g0, bt0);
    gemm_kernel<64,128,2><<<dim3(M_TOTAL/256, 2), 256, sm2>>>(b2, g1, bt1);

    finalize_kernel<<<(BB*128*SS)/256, 256>>>(out_feat, g2, bt2);
}

// round 17
// speedup vs baseline: 1.0549x; 1.0167x over previous
#include <cuda_runtime.h>

#define BB 8
#define NN 4096
#define SS 1024
#define KK 32
#define M_TOTAL (BB*SS*KK)   // 262144
#define NBS (BB*SS)          // 8192

// ---------------- device scratch ----------------
__device__ float g_newxyz[NBS*3];            // (B,S,3)
__device__ float g_X0[67*M_TOTAL];
__device__ float g_Y0[64*M_TOTAL];
__device__ float g_Y1[64*M_TOTAL];
__device__ float g_mx2[128*NBS];
__device__ float g_mn2[128*NBS];
__device__ float2 g_WT0p[67*64];             // W transposed, duplicated pairs {w,w}
__device__ float2 g_WT1p[64*64];
__device__ float2 g_WT2p[64*128];
__device__ float g_sum0[64], g_sq0[64], g_sum1[64], g_sq1[64], g_sum2[128], g_sq2[128];

// ---------------- f32x2 packed helpers (bitwise identical per lane) ----------------
__device__ __forceinline__ unsigned long long ffma2(unsigned long long x, unsigned long long w,
                                                    unsigned long long a) {
    unsigned long long d;
    asm("fma.rn.f32x2 %0, %1, %2, %3;" : "=l"(d) : "l"(w), "l"(x), "l"(a));
    return d;
}
__device__ __forceinline__ unsigned long long add2(unsigned long long a, unsigned long long b) {
    unsigned long long d;
    asm("add.rn.f32x2 %0, %1, %2;" : "=l"(d) : "l"(a), "l"(b));
    return d;
}
__device__ __forceinline__ unsigned long long mul2(unsigned long long a, unsigned long long b) {
    unsigned long long d;
    asm("mul.rn.f32x2 %0, %1, %2;" : "=l"(d) : "l"(a), "l"(b));
    return d;
}
__device__ __forceinline__ unsigned long long pack2(float w) {
    unsigned long long d;
    asm("mov.b64 %0, {%1, %1};" : "=l"(d) : "f"(w));
    return d;
}
__device__ __forceinline__ unsigned long long packab(float a, float b) {
    unsigned long long d;
    asm("mov.b64 %0, {%1, %2};" : "=l"(d) : "f"(a), "f"(b));
    return d;
}
__device__ __forceinline__ float2 unpack2(unsigned long long v) {
    float2 r;
    asm("mov.b64 {%0, %1}, %2;" : "=f"(r.x), "=f"(r.y) : "l"(v));
    return r;
}
__device__ __forceinline__ float fneg(float x) {
    return __int_as_float(__float_as_int(x) ^ 0x80000000);
}
// BN affine from raw sums: identical formula/order everywhere -> bitwise identical
__device__ __forceinline__ void bn_affine(float sum, float sq, float g, float bt,
                                          float& a, float& c) {
    const float invM = 1.0f / (float)M_TOTAL;
    float mean = sum * invM;
    float var  = __fmaf_rn(-mean, mean, sq * invM);
    float inv  = 1.0f / sqrtf(var + 1e-5f);
    a = g * inv;
    c = __fmaf_rn(-mean, a, bt);
}

// ---------------- FPS ----------------
// one block per batch, 1024 threads, 4 points/thread packed as 2 f32x2 pairs.
__global__ void __launch_bounds__(1024) fps_kernel(const float* __restrict__ xyz,
                                                   float* __restrict__ out_newxyz_T)
{
    const int b = blockIdx.x;
    const int tid = threadIdx.x;
    const int lane = tid & 31, wid = tid >> 5;
    __shared__ unsigned sd[2][32];
    __shared__ unsigned si[2][32];
    extern __shared__ float sxyz[];   // 3*NN floats

    const float* xb = xyz + (size_t)b*3*NN;
    unsigned long long pxp[2], pyp[2], pzp[2];
    float dmin[4];
    {
        float px[4], py[4], pz[4];
#pragma unroll
        for (int j = 0; j < 4; ++j) {
            int i = tid + (j << 10);
            px[j] = xb[i]; py[j] = xb[NN + i]; pz[j] = xb[2*NN + i];
            sxyz[i] = px[j]; sxyz[NN + i] = py[j]; sxyz[2*NN + i] = pz[j];
            dmin[j] = 1e10f;
        }
        pxp[0] = packab(px[0], px[1]); pxp[1] = packab(px[2], px[3]);
        pyp[0] = packab(py[0], py[1]); pyp[1] = packab(py[2], py[3]);
        pzp[0] = packab(pz[0], pz[1]); pzp[1] = packab(pz[2], pz[3]);
    }
    __syncthreads();
    float cx = sxyz[0], cy = sxyz[NN], cz = sxyz[2*NN];
    if (tid == 0) {
        int o3 = (b*SS + 0)*3;
        g_newxyz[o3+0] = cx; g_newxyz[o3+1] = cy; g_newxyz[o3+2] = cz;
        out_newxyz_T[(b*3+0)*SS + 0] = cx;
        out_newxyz_T[(b*3+1)*SS + 0] = cy;
        out_newxyz_T[(b*3+2)*SS + 0] = cz;
    }

    for (int it = 1; it < SS; ++it) {
        const unsigned long long nx = pack2(fneg(cx));
        const unsigned long long ny = pack2(fneg(cy));
        const unsigned long long nz = pack2(fneg(cz));
        float d[4];
#pragma unroll
        for (int p = 0; p < 2; ++p) {
            unsigned long long dx = add2(pxp[p], nx);
            unsigned long long dy = add2(pyp[p], ny);
            unsigned long long dz = add2(pzp[p], nz);
            unsigned long long dd = add2(add2(mul2(dx,dx), mul2(dy,dy)), mul2(dz,dz));
            float2 f = unpack2(dd);
            d[2*p] = f.x; d[2*p+1] = f.y;
        }
#pragma unroll
        for (int j = 0; j < 4; ++j) dmin[j] = fminf(dmin[j], d[j]);
        float m = fmaxf(fmaxf(dmin[0], dmin[1]), fmaxf(dmin[2], dmin[3]));
        int j = (dmin[0] == m) ? 0 : ((dmin[1] == m) ? 1 : ((dmin[2] == m) ? 2 : 3));
        unsigned db   = __float_as_uint(m);
        unsigned idxv = (unsigned)(tid + (j << 10));
        unsigned wd = __reduce_max_sync(0xffffffffu, db);
        unsigned wi = __reduce_min_sync(0xffffffffu, (db == wd) ? idxv : 0xffffffffu);
        int buf = it & 1;
        if (lane == 0) { sd[buf][wid] = wd; si[buf][wid] = wi; }
        __syncthreads();
        unsigned d2 = sd[buf][lane], i2 = si[buf][lane];
        unsigned gd  = __reduce_max_sync(0xffffffffu, d2);
        unsigned far = __reduce_min_sync(0xffffffffu, (d2 == gd) ? i2 : 0xffffffffu);
        cx = sxyz[far]; cy = sxyz[NN + far]; cz = sxyz[2*NN + far];
        if (tid == (int)(far & 1023u)) {
            int o3 = (b*SS + it)*3;
            g_newxyz[o3+0] = cx; g_newxyz[o3+1] = cy; g_newxyz[o3+2] = cz;
            out_newxyz_T[(b*3+0)*SS + it] = cx;
            out_newxyz_T[(b*3+1)*SS + it] = cy;
            out_newxyz_T[(b*3+2)*SS + it] = cz;
        }
    }
}

// ---------------- fused ball query + gather (one warp per center) ----------------
// Indices stay in per-warp smem (no g_ballidx round trip). Tail block preps
// W pairs and zeroes BN stats.
__global__ void __launch_bounds__(256) ball_gather_kernel(const float* __restrict__ xyz,
                                                          const float* __restrict__ points,
                                                          const float* __restrict__ W0,
                                                          const float* __restrict__ W1,
                                                          const float* __restrict__ W2)
{
    if (blockIdx.x == NBS/8) {
        const int t = threadIdx.x;
        if (t < 64)  { g_sum0[t]=0.f; g_sq0[t]=0.f; g_sum1[t]=0.f; g_sq1[t]=0.f; }
        if (t < 128) { g_sum2[t]=0.f; g_sq2[t]=0.f; }
        for (int i = t; i < 67*64; i += 256) {
            int o = i & 63, c = i >> 6;
            float w = __ldg(W0 + o*67 + c);
            g_WT0p[i] = make_float2(w, w);
        }
        for (int i = t; i < 64*64; i += 256) {
            int o = i & 63, c = i >> 6;
            float w = __ldg(W1 + o*64 + c);
            g_WT1p[i] = make_float2(w, w);
        }
        for (int i = t; i < 64*128; i += 256) {
            int o = i & 127, c = i >> 7;
            float w = __ldg(W2 + o*64 + c);
            g_WT2p[i] = make_float2(w, w);
        }
        return;
    }
    __shared__ int sIdx[8][KK];
    const int wib  = threadIdx.x >> 5;
    const int lane = threadIdx.x & 31;
    const int w = blockIdx.x*8 + wib;
    if (w >= NBS) return;
    const int b = w >> 10;

    const float cx = g_newxyz[w*3+0], cy = g_newxyz[w*3+1], cz = g_newxyz[w*3+2];
    const float s2 = __fadd_rn(__fadd_rn(__fmul_rn(cx,cx), __fmul_rn(cy,cy)), __fmul_rn(cz,cz));
    const float R2 = (float)(0.4*0.4);
    const float* xb = xyz + (size_t)b*3*NN;
    int total = 0, firstn = 0;
    int* buf = sIdx[wib];

    for (int base = 0; base < NN; base += 32) {
        int n = base + lane;
        float px = __ldg(xb + n), py = __ldg(xb + NN + n), pz = __ldg(xb + 2*NN + n);
        float n2  = __fadd_rn(__fadd_rn(__fmul_rn(px,px), __fmul_rn(py,py)), __fmul_rn(pz,pz));
        float dot = __fadd_rn(__fadd_rn(__fmul_rn(cx,px), __fmul_rn(cy,py)), __fmul_rn(cz,pz));
        float d   = __fadd_rn(__fadd_rn(__fmul_rn(-2.0f, dot), s2), n2);
        bool pred = !(d > R2);
        unsigned mask = __ballot_sync(0xffffffffu, pred);
        if (mask) {
            if (total == 0) firstn = base + __ffs(mask) - 1;
            if (pred) {
                int pos = total + __popc(mask & ((1u << lane) - 1u));
                if (pos < KK) buf[pos] = n;
            }
            total += __popc(mask);
            if (total >= KK) break;
        }
    }
    for (int p = total + lane; p < KK; p += 32) buf[p] = firstn;
    __syncwarp();
    const int idx = buf[lane];

    // gather / concat -> X0 (lane = k)
    const size_t m0 = (size_t)w * KK;
    g_X0[(size_t)0*M_TOTAL + m0 + lane] = __fsub_rn(__ldg(&xb[idx]),        cx);
    g_X0[(size_t)1*M_TOTAL + m0 + lane] = __fsub_rn(__ldg(&xb[NN + idx]),   cy);
    g_X0[(size_t)2*M_TOTAL + m0 + lane] = __fsub_rn(__ldg(&xb[2*NN + idx]), cz);
    const float* pb = points + (size_t)b*64*NN + idx;
#pragma unroll 8
    for (int d = 0; d < 64; ++d)
        g_X0[(size_t)(3+d)*M_TOTAL + m0 + lane] = __ldg(pb + (size_t)d*NN);
}

// ---------------- GEMM (chunked, double-buffered, remainder-aware) ----------------
// 256 threads (tx=lane, ty=warp 0..7). Tile: 256 cols x 64 channels; per-thread
// 8 cols x 8 channels. K in 16-row chunks, last chunk REM rows (exact).
// gridDim.y selects the 64-channel half for LAYER 2.
// LAYER 1,2: BN affine computed in-block from raw sums (no stats kernel),
// fused BN+ReLU on X staging. LAYER 2: fused max/min pool.
template<int CIN, int COUT, int LAYER>
__global__ void __launch_bounds__(256, 2) gemm_kernel(const float* __restrict__ bias,
                                                      const float* __restrict__ gamma,
                                                      const float* __restrict__ beta)
{
    constexpr int NCH = (CIN + 15) / 16;
    constexpr int REM = CIN - (NCH - 1) * 16;
    const float* Xg = (LAYER==0) ? g_X0 : ((LAYER==1) ? g_Y0 : g_Y1);
    float* Yg       = (LAYER==0) ? g_Y0 : g_Y1;           // unused for LAYER==2
    const float2* WTp = (LAYER==0) ? g_WT0p : ((LAYER==1) ? g_WT1p : g_WT2p);
    float* sumArr   = (LAYER==0) ? g_sum0 : ((LAYER==1) ? g_sum1 : g_sum2);
    float* sqArr    = (LAYER==0) ? g_sq0  : ((LAYER==1) ? g_sq1  : g_sq2);
    const float* sumPrev = (LAYER==1) ? g_sum0 : g_sum1;
    const float* sqPrev  = (LAYER==1) ? g_sq0  : g_sq1;

    extern __shared__ unsigned long long smem_u64[];
    unsigned long long* Wp = smem_u64;               // CIN*64 packed pairs
    float* Xs  = (float*)(smem_u64 + CIN*64);        // 2 * 16*256 floats
    float* as_ = Xs + 2*4096;                        // CIN
    float* cs_ = as_ + CIN;                          // CIN

    const int tid = threadIdx.x;
    const int m0  = blockIdx.x * 256;
    const int ob  = blockIdx.y * 64;

    if (LAYER >= 1) {
        if (tid < CIN) {
            float a, c;
            bn_affine(sumPrev[tid], sqPrev[tid], __ldg(gamma + tid), __ldg(beta + tid), a, c);
            as_[tid] = a; cs_[tid] = c;
        }
    }
    for (int i = tid; i < CIN*64; i += 256) {
        int c = i >> 6, o = i & 63;
        ((float2*)Wp)[i] = __ldg(WTp + c*COUT + ob + o);
    }
    __syncthreads();

    // stage chunk 0
#pragma unroll
    for (int j = 0; j < 4; ++j) {
        int i = tid + (j << 8);
        int cl = i >> 6, q = i & 63;
        float4 v = __ldg((const float4*)(Xg + (size_t)cl*M_TOTAL + m0) + q);
        if (LAYER >= 1) {
            float a = as_[cl], cc = cs_[cl];
            v.x = fmaxf(0.f, __fmaf_rn(v.x, a, cc));
            v.y = fmaxf(0.f, __fmaf_rn(v.y, a, cc));
            v.z = fmaxf(0.f, __fmaf_rn(v.z, a, cc));
            v.w = fmaxf(0.f, __fmaf_rn(v.w, a, cc));
        }
        *(float4*)(Xs + cl*256 + (q << 2)) = v;
    }
    __syncthreads();

    const int tx = tid & 31, ty = tid >> 5;
    unsigned long long acc[8][4];
#pragma unroll
    for (int r = 0; r < 8; ++r)
#pragma unroll
        for (int q = 0; q < 4; ++q) acc[r][q] = 0ull;

    int buf = 0;
#pragma unroll 1
    for (int ch = 0; ch < NCH - 1; ++ch) {
        const int nc0 = (ch + 1) << 4;
        float4 pre[4];
#pragma unroll
        for (int j = 0; j < 4; ++j) {
            int i = tid + (j << 8);
            int c = nc0 + (i >> 6);
            pre[j] = make_float4(0.f, 0.f, 0.f, 0.f);
            if (c < CIN)
                pre[j] = __ldg((const float4*)(Xg + (size_t)c*M_TOTAL + m0) + (i & 63));
        }
        const float* xb = Xs + buf*4096;
        const unsigned long long* wb = Wp + (ch << 4)*64 + (ty << 3);
#pragma unroll
        for (int kk = 0; kk < 16; ++kk) {
            ulonglong2 xA = *(const ulonglong2*)(xb + kk*256 + (tx << 2));
            ulonglong2 xB = *(const ulonglong2*)(xb + kk*256 + 128 + (tx << 2));
            const ulonglong2* wp = (const ulonglong2*)(wb + kk*64);
            ulonglong2 w01 = wp[0], w23 = wp[1], w45 = wp[2], w67 = wp[3];
            unsigned long long xv[4] = {xA.x, xA.y, xB.x, xB.y};
            unsigned long long wv[8] = {w01.x, w01.y, w23.x, w23.y,
                                        w45.x, w45.y, w67.x, w67.y};
#pragma unroll
            for (int r = 0; r < 8; ++r)
#pragma unroll
                for (int q = 0; q < 4; ++q)
                    acc[r][q] = ffma2(xv[q], wv[r], acc[r][q]);
        }
        {
            float* xd = Xs + (buf ^ 1)*4096;
#pragma unroll
            for (int j = 0; j < 4; ++j) {
                int i = tid + (j << 8);
                int cl = i >> 6, q = i & 63;
                float4 v = pre[j];
                if (LAYER >= 1) {
                    int c = nc0 + cl;
                    if (c < CIN) {
                        float a = as_[c], cc = cs_[c];
                        v.x = fmaxf(0.f, __fmaf_rn(v.x, a, cc));
                        v.y = fmaxf(0.f, __fmaf_rn(v.y, a, cc));
                        v.z = fmaxf(0.f, __fmaf_rn(v.z, a, cc));
                        v.w = fmaxf(0.f, __fmaf_rn(v.w, a, cc));
                    }
                }
                *(float4*)(xd + cl*256 + (q << 2)) = v;
            }
        }
        __syncthreads();
        buf ^= 1;
    }
    // final chunk: REM rows only (skipped rows would be exact zeros)
    {
        const float* xb = Xs + buf*4096;
        const unsigned long long* wb = Wp + ((NCH-1) << 4)*64 + (ty << 3);
#pragma unroll
        for (int kk = 0; kk < REM; ++kk) {
            ulonglong2 xA = *(const ulonglong2*)(xb + kk*256 + (tx << 2));
            ulonglong2 xB = *(const ulonglong2*)(xb + kk*256 + 128 + (tx << 2));
            const ulonglong2* wp = (const ulonglong2*)(wb + kk*64);
            ulonglong2 w01 = wp[0], w23 = wp[1], w45 = wp[2], w67 = wp[3];
            unsigned long long xv[4] = {xA.x, xA.y, xB.x, xB.y};
            unsigned long long wv[8] = {w01.x, w01.y, w23.x, w23.y,
                                        w45.x, w45.y, w67.x, w67.y};
#pragma unroll
            for (int r = 0; r < 8; ++r)
#pragma unroll
                for (int q = 0; q < 4; ++q)
                    acc[r][q] = ffma2(xv[q], wv[r], acc[r][q]);
        }
    }

    const int m0q = m0 >> 5;   // first k-group of this tile (8 groups)
#pragma unroll
    for (int r = 0; r < 8; ++r) {
        int ch = ob + (ty << 3) + r;
        float bv = __ldg(bias + ch);
        float o[8];
        {
            float2 p0 = unpack2(acc[r][0]), p1 = unpack2(acc[r][1]);
            float2 p2 = unpack2(acc[r][2]), p3 = unpack2(acc[r][3]);
            o[0]=p0.x+bv; o[1]=p0.y+bv; o[2]=p1.x+bv; o[3]=p1.y+bv;
            o[4]=p2.x+bv; o[5]=p2.y+bv; o[6]=p3.x+bv; o[7]=p3.y+bv;
        }
        float s = 0.f, s2 = 0.f;
#pragma unroll
        for (int j = 0; j < 8; ++j) {
            s += o[j];
            s2 = __fmaf_rn(o[j], o[j], s2);
        }
        if (LAYER < 2) {
            float* yp = Yg + (size_t)ch*M_TOTAL + m0 + (tx << 2);
            *(float4*)yp         = make_float4(o[0],o[1],o[2],o[3]);
            *(float4*)(yp + 128) = make_float4(o[4],o[5],o[6],o[7]);
        } else {
            // pool over K: quad A in group tx>>3, quad B in group 4+(tx>>3)
            float mxA = fmaxf(fmaxf(o[0],o[1]), fmaxf(o[2],o[3]));
            float mnA = fminf(fminf(o[0],o[1]), fminf(o[2],o[3]));
            float mxB = fmaxf(fmaxf(o[4],o[5]), fmaxf(o[6],o[7]));
            float mnB = fminf(fminf(o[4],o[5]), fminf(o[6],o[7]));
#pragma unroll
            for (int off = 1; off < 8; off <<= 1) {
                mxA = fmaxf(mxA, __shfl_xor_sync(0xffffffffu, mxA, off));
                mnA = fminf(mnA, __shfl_xor_sync(0xffffffffu, mnA, off));
                mxB = fmaxf(mxB, __shfl_xor_sync(0xffffffffu, mxB, off));
                mnB = fminf(mnB, __shfl_xor_sync(0xffffffffu, mnB, off));
            }
            if ((tx & 7) == 0) {
                int bsA = m0q + (tx >> 3);
                int bsB = m0q + 4 + (tx >> 3);
                g_mx2[ch*NBS + bsA] = mxA;
                g_mn2[ch*NBS + bsA] = mnA;
                g_mx2[ch*NBS + bsB] = mxB;
                g_mn2[ch*NBS + bsB] = mnB;
            }
        }
#pragma unroll
        for (int off = 16; off > 0; off >>= 1) {
            s  += __shfl_xor_sync(0xffffffffu, s,  off);
            s2 += __shfl_xor_sync(0xffffffffu, s2, off);
        }
        if (tx == 0) { atomicAdd(sumArr + ch, s); atomicAdd(sqArr + ch, s2); }
    }
}

// ---------------- finalize: BN affine from sums + ReLU on pooled extrema ----------------
// max_k relu(a*y+c) == relu(a*(a>=0 ? max_k y : min_k y) + c)  (fmaf monotone in y)
__global__ void __launch_bounds__(256) finalize_kernel(float* __restrict__ out,
                                                       const float* __restrict__ gamma,
                                                       const float* __restrict__ beta)
{
    int gid = blockIdx.x * blockDim.x + threadIdx.x;
    if (gid >= BB*128*SS) return;
    int s = gid & (SS-1);
    int o = (gid >> 10) & 127;
    int b = gid >> 17;
    float a, c;
    bn_affine(g_sum2[o], g_sq2[o], __ldg(gamma + o), __ldg(beta + o), a, c);
    int bs = (b << 10) + s;
    float v = (a >= 0.f) ? g_mx2[o*NBS + bs] : g_mn2[o*NBS + bs];
    out[gid] = fmaxf(0.f, __fmaf_rn(v, a, c));
}

// ---------------- launch ----------------
extern "C" void kernel_launch(void* const* d_in, const int* in_sizes, int n_in,
                              void* d_out, int out_size)
{
    const float* xyz    = (const float*)d_in[0];
    const float* points = (const float*)d_in[1];
    const float* W0  = (const float*)d_in[2];
    const float* b0  = (const float*)d_in[3];
    const float* g0  = (const float*)d_in[4];
    const float* bt0 = (const float*)d_in[5];
    const float* W1  = (const float*)d_in[6];
    const float* b1  = (const float*)d_in[7];
    const float* g1  = (const float*)d_in[8];
    const float* bt1 = (const float*)d_in[9];
    const float* W2  = (const float*)d_in[10];
    const float* b2  = (const float*)d_in[11];
    const float* g2  = (const float*)d_in[12];
    const float* bt2 = (const float*)d_in[13];

    float* out = (float*)d_out;
    float* out_feat = out + BB*3*SS;

    const int smf = 3*NN*4;                              // 49152 (fps xyz stage)
    const int sm0 = 67*64*8 + 2*4096*4 + 2*67*4;         // 67608
    const int sm1 = 64*64*8 + 2*4096*4 + 2*64*4;         // 66048
    const int sm2 = sm1;
    cudaFuncSetAttribute(fps_kernel, cudaFuncAttributeMaxDynamicSharedMemorySize, smf);
    cudaFuncSetAttribute(gemm_kernel<67,64,0>,  cudaFuncAttributeMaxDynamicSharedMemorySize, sm0);
    cudaFuncSetAttribute(gemm_kernel<64,64,1>,  cudaFuncAttributeMaxDynamicSharedMemorySize, sm1);
    cudaFuncSetAttribute(gemm_kernel<64,128,2>, cudaFuncAttributeMaxDynamicSharedMemorySize, sm2);

    fps_kernel<<<BB, 1024, smf>>>(xyz, out);
    ball_gather_kernel<<<NBS/8 + 1, 256>>>(xyz, points, W0, W1, W2);

    gemm_kernel<67,64,0><<<dim3(M_TOTAL/256, 1), 256, sm0>>>(b0, nullptr, nullptr);
    gemm_kernel<64,64,1><<<dim3(M_TOTAL/256, 1), 256, sm1>>>(b1, g0, bt0);
    gemm_kernel<64,128,2><<<dim3(M_TOTAL/256, 2), 256, sm2>>>(b2, g1, bt1);

    finalize_kernel<<<(BB*128*SS)/256, 256>>>(out_feat, g2, bt2);
}